// round 6
// baseline (speedup 1.0000x reference)
#include <cuda_runtime.h>
#include <cuda_bf16.h>
#include <cstdint>

// ============================================================================
// R6: QKV & QK via int8 IMMA (m16n8k32, s32 acc) with 2-term fixed-point split
//     v*S ~= a1*128 + a2   (a1,a2 int8; a2 in [-64,63])
//     C = (C11*16384 + Cmid*128 + C22) / (Sa*Sb)   -- 4 IMMA terms, exact acc.
// PV stays bf16 3-term mma (P's small probabilities need floating point).
// Hypothesis under test: IMMA.16832 = 2x HMMA.16816 MAC rate (same issue slot).
// ============================================================================

using bf16 = __nv_bfloat16;

// ---------------- scratch ----------------------------------------------------
__device__ __align__(256) int8_t g_x1[8192 * 1024], g_x2[8192 * 1024];
__device__ __align__(256) int8_t g_W1[3 * 1024 * 1024], g_W2[3 * 1024 * 1024];
__device__ __align__(256) int8_t g_Q1[8192 * 1024], g_Q2[8192 * 1024];
__device__ __align__(256) int8_t g_K1[8192 * 1024], g_K2[8192 * 1024];
__device__ __align__(256) bf16 g_Vthi[4 * 1024 * 2048], g_Vtlo[4 * 1024 * 2048];
__device__ __align__(256) float g_S[4 * 2048 * 2048];
__device__ __align__(256) bf16 g_Phi[4 * 2048 * 2048], g_Plo[4 * 2048 * 2048];

// Scales
#define S_X   2048.0f
#define S_W   65536.0f
#define S_QK  2048.0f
#define INV_QKV (1.0f / (2048.0f * 65536.0f))
#define INV_QK  (1.0f / (2048.0f * 2048.0f))

// ---------------- PTX helpers -------------------------------------------------
__device__ __forceinline__ uint32_t smem_u32(const void* p) {
    uint32_t a;
    asm("{ .reg .u64 t; cvta.to.shared.u64 t, %1; cvt.u32.u64 %0, t; }" : "=r"(a) : "l"(p));
    return a;
}
__device__ __forceinline__ void cp16(uint32_t dst, const void* src) {
    asm volatile("cp.async.cg.shared.global [%0], [%1], 16;" :: "r"(dst), "l"(src));
}
#define CP_COMMIT() asm volatile("cp.async.commit_group;" ::: "memory")

__device__ __forceinline__ void ldm4(uint32_t* r, uint32_t a) {
    asm volatile("ldmatrix.sync.aligned.m8n8.x4.shared.b16 {%0,%1,%2,%3}, [%4];"
                 : "=r"(r[0]), "=r"(r[1]), "=r"(r[2]), "=r"(r[3]) : "r"(a));
}
__device__ __forceinline__ void mma_bf16(float* c, const uint32_t* a, uint32_t b0, uint32_t b1) {
    asm volatile(
        "mma.sync.aligned.m16n8k16.row.col.f32.bf16.bf16.f32 "
        "{%0,%1,%2,%3}, {%4,%5,%6,%7}, {%8,%9}, {%0,%1,%2,%3};"
        : "+f"(c[0]), "+f"(c[1]), "+f"(c[2]), "+f"(c[3])
        : "r"(a[0]), "r"(a[1]), "r"(a[2]), "r"(a[3]), "r"(b0), "r"(b1));
}
__device__ __forceinline__ void imma(int* c, const uint32_t* a, uint32_t b0, uint32_t b1) {
    asm volatile(
        "mma.sync.aligned.m16n8k32.row.col.s32.s8.s8.s32 "
        "{%0,%1,%2,%3}, {%4,%5,%6,%7}, {%8,%9}, {%0,%1,%2,%3};"
        : "+r"(c[0]), "+r"(c[1]), "+r"(c[2]), "+r"(c[3])
        : "r"(a[0]), "r"(a[1]), "r"(a[2]), "r"(a[3]), "r"(b0), "r"(b1));
}

__device__ __forceinline__ void split_store(float v, bf16* hi, bf16* lo, size_t o) {
    bf16 h = __float2bfloat16(v);
    hi[o] = h;
    lo[o] = __float2bfloat16(v - __bfloat162float(h));
}
// int8 pair quantization: v*S -> (hi, lo), v*S ~= hi*128 + lo
__device__ __forceinline__ void quant2(float v, float S, int& hi, int& lo) {
    int q = __float2int_rn(v * S);
    q = max(-16191, min(16191, q));
    hi = (q + 64) >> 7;          // hi in [-127, 126]
    lo = q - (hi << 7);          // lo in [-64, 63]
}

// ============================================================================
//                        int8 GEMM (QKV / QK phases)
// CTA tile 128x64, 256 thr, warp 64x16 (wm in {0,1}, wn in {0..3}), K-stage 64.
// smem per stage: A1,A2 (128 rows) + B1,B2 (64 rows); each row-k32-block has
// 48B row stride (12 words: 12r+c distinct mod 32 -> conflict-free LDS).
// ============================================================================
#define I8_A_BLK  6144                 // one k32 block of A term: 128*48
#define I8_B_BLK  3072                 // one k32 block of B term: 64*48
#define I8_A_SZ   (2 * I8_A_BLK)       // 12288 (two k32 blocks)
#define I8_B_SZ   (2 * I8_B_BLK)       // 6144
#define I8_STG    (2 * I8_A_SZ + 2 * I8_B_SZ)   // 36864
#define I8_SMEM   (2 * I8_STG)                  // 73728

// MODE 0: QKV (z: 0->Q int8 pair, 1->K int8 pair, 2->V bf16-split transposed)
// MODE 1: QK  (z=batch): g_S = C*invSS/32
template <int MODE>
__device__ __forceinline__ void i8_gemm_body(
    const int8_t* __restrict__ A1, const int8_t* __restrict__ A2, int lda,
    const int8_t* __restrict__ B1, const int8_t* __restrict__ B2, int ldb,
    int K, float invSS)
{
    extern __shared__ char sm[];
    const uint32_t smb = smem_u32(sm);
    const int tid = threadIdx.x, lane = tid & 31, wid = tid >> 5;
    const int g = lane >> 2, lq = lane & 3;
    const int wm = wid & 1, wn = wid >> 1;
    const int row0 = blockIdx.y * 128, col0 = blockIdx.x * 64;

    int c11[4][2][4], cmid[4][2][4], c22[4][2][4];
    #pragma unroll
    for (int i = 0; i < 4; ++i)
        #pragma unroll
        for (int j = 0; j < 2; ++j)
            #pragma unroll
            for (int k = 0; k < 4; ++k) { c11[i][j][k] = 0; cmid[i][j][k] = 0; c22[i][j][k] = 0; }

    // loader: A chunks idx=tid, tid+256 ; B chunks idx=tid
    const int ar = tid >> 2;            // 0..63 (+64 second)
    const int akb = (tid & 3) * 16;     // 0,16,32,48
    const uint32_t a_dst = (akb >> 5) * I8_A_BLK + ar * 48 + (akb & 31);
    const int br = tid >> 2;            // 0..63
    const uint32_t b_dst = (akb >> 5) * I8_B_BLK + br * 48 + (akb & 31);

    auto load_stage = [&](int sbuf, int k0) {
        const uint32_t sb = smb + sbuf * I8_STG;
        const size_t ga  = (size_t)(row0 + ar) * lda + k0 + akb;
        const size_t ga2 = (size_t)(row0 + ar + 64) * lda + k0 + akb;
        const size_t gb  = (size_t)(col0 + br) * ldb + k0 + akb;
        cp16(sb + a_dst,                     A1 + ga);
        cp16(sb + a_dst + 64 * 48,           A1 + ga2);
        cp16(sb + I8_A_SZ + a_dst,           A2 + ga);
        cp16(sb + I8_A_SZ + a_dst + 64 * 48, A2 + ga2);
        cp16(sb + 2 * I8_A_SZ + b_dst,            B1 + gb);
        cp16(sb + 2 * I8_A_SZ + I8_B_SZ + b_dst,  B2 + gb);
        CP_COMMIT();
    };

    const int ns = K >> 6;   // 64 K per stage
    load_stage(0, 0);

    // fragment LDS offsets
    const uint32_t a_row = (uint32_t)(wm * 64) * 48 + g * 48 + lq * 4;
    const uint32_t b_row = (uint32_t)(wn * 16) * 48 + g * 48 + lq * 4;

    for (int s = 0; s < ns; ++s) {
        if (s + 1 < ns) {
            load_stage((s + 1) & 1, (s + 1) * 64);
            asm volatile("cp.async.wait_group 1;" ::: "memory");
        } else {
            asm volatile("cp.async.wait_group 0;" ::: "memory");
        }
        __syncthreads();

        const uint32_t sb = smb + (s & 1) * I8_STG;
        #pragma unroll
        for (int sub = 0; sub < 2; ++sub) {
            // B fragments: [term][nt][2]
            uint32_t bf[2][2][2];
            #pragma unroll
            for (int nt = 0; nt < 2; ++nt) {
                const uint32_t bb1 = sb + 2 * I8_A_SZ + sub * I8_B_BLK + b_row + nt * 8 * 48;
                const uint32_t bb2 = bb1 + I8_B_SZ;
                asm volatile("ld.shared.b32 %0, [%1];" : "=r"(bf[0][nt][0]) : "r"(bb1));
                asm volatile("ld.shared.b32 %0, [%1];" : "=r"(bf[0][nt][1]) : "r"(bb1 + 16));
                asm volatile("ld.shared.b32 %0, [%1];" : "=r"(bf[1][nt][0]) : "r"(bb2));
                asm volatile("ld.shared.b32 %0, [%1];" : "=r"(bf[1][nt][1]) : "r"(bb2 + 16));
            }
            #pragma unroll
            for (int mt = 0; mt < 4; ++mt) {
                const uint32_t aa1 = sb + sub * I8_A_BLK + a_row + mt * 16 * 48;
                const uint32_t aa2 = aa1 + I8_A_SZ;
                uint32_t af1[4], af2[4];
                asm volatile("ld.shared.b32 %0, [%1];" : "=r"(af1[0]) : "r"(aa1));
                asm volatile("ld.shared.b32 %0, [%1];" : "=r"(af1[1]) : "r"(aa1 + 8 * 48));
                asm volatile("ld.shared.b32 %0, [%1];" : "=r"(af1[2]) : "r"(aa1 + 16));
                asm volatile("ld.shared.b32 %0, [%1];" : "=r"(af1[3]) : "r"(aa1 + 8 * 48 + 16));
                asm volatile("ld.shared.b32 %0, [%1];" : "=r"(af2[0]) : "r"(aa2));
                asm volatile("ld.shared.b32 %0, [%1];" : "=r"(af2[1]) : "r"(aa2 + 8 * 48));
                asm volatile("ld.shared.b32 %0, [%1];" : "=r"(af2[2]) : "r"(aa2 + 16));
                asm volatile("ld.shared.b32 %0, [%1];" : "=r"(af2[3]) : "r"(aa2 + 8 * 48 + 16));
                #pragma unroll
                for (int nt = 0; nt < 2; ++nt) {
                    imma(c11[mt][nt],  af1, bf[0][nt][0], bf[0][nt][1]);
                    imma(cmid[mt][nt], af1, bf[1][nt][0], bf[1][nt][1]);
                    imma(cmid[mt][nt], af2, bf[0][nt][0], bf[0][nt][1]);
                    imma(c22[mt][nt],  af2, bf[1][nt][0], bf[1][nt][1]);
                }
            }
        }
        __syncthreads();
    }

    // ---- epilogue ----
    const int z = blockIdx.z;
    #pragma unroll
    for (int mt = 0; mt < 4; ++mt)
        #pragma unroll
        for (int nt = 0; nt < 2; ++nt) {
            float v[4];
            #pragma unroll
            for (int i = 0; i < 4; ++i)
                v[i] = fmaf((float)c11[mt][nt][i], 16384.f,
                       fmaf((float)cmid[mt][nt][i], 128.f,
                            (float)c22[mt][nt][i])) * invSS;
            const int gr = row0 + wm * 64 + mt * 16 + g;
            const int gc = col0 + wn * 16 + nt * 8 + lq * 2;
            if (MODE == 0) {
                if (z == 2) {
                    const int b0 = gr >> 11, t0 = gr & 2047;
                    const size_t o = ((size_t)(b0 * 1024 + gc)) * 2048 + t0;
                    split_store(v[0], g_Vthi, g_Vtlo, o);
                    split_store(v[1], g_Vthi, g_Vtlo, o + 2048);
                    split_store(v[2], g_Vthi, g_Vtlo, o + 8);
                    split_store(v[3], g_Vthi, g_Vtlo, o + 2048 + 8);
                } else {
                    int8_t* d1 = (z == 0) ? g_Q1 : g_K1;
                    int8_t* d2 = (z == 0) ? g_Q2 : g_K2;
                    int h0, l0, h1, l1;
                    quant2(v[0], S_QK, h0, l0); quant2(v[1], S_QK, h1, l1);
                    *(char2*)(d1 + (size_t)gr * 1024 + gc) = make_char2((char)h0, (char)h1);
                    *(char2*)(d2 + (size_t)gr * 1024 + gc) = make_char2((char)l0, (char)l1);
                    quant2(v[2], S_QK, h0, l0); quant2(v[3], S_QK, h1, l1);
                    *(char2*)(d1 + (size_t)(gr + 8) * 1024 + gc) = make_char2((char)h0, (char)h1);
                    *(char2*)(d2 + (size_t)(gr + 8) * 1024 + gc) = make_char2((char)l0, (char)l1);
                }
            } else {
                float* p = g_S + ((size_t)z << 22) + (size_t)gr * 2048 + gc;
                *(float2*)p             = make_float2(v[0] * 0.03125f, v[1] * 0.03125f);
                *(float2*)(p + 8*2048)  = make_float2(v[2] * 0.03125f, v[3] * 0.03125f);
            }
        }
}

__global__ void __launch_bounds__(256)
qkv_i8_kernel()
{
    const int z = blockIdx.z;
    i8_gemm_body<0>(g_x1, g_x2, 1024,
                    g_W1 + (size_t)z * 1024 * 1024, g_W2 + (size_t)z * 1024 * 1024, 1024,
                    1024, INV_QKV);
}

__global__ void __launch_bounds__(256)
qk_i8_kernel()
{
    const size_t bo = (size_t)blockIdx.z << 21;
    i8_gemm_body<1>(g_Q1 + bo, g_Q2 + bo, 1024,
                    g_K1 + bo, g_K2 + bo, 1024,
                    1024, INV_QK);
}

// ============================================================================
//                    PV: bf16 3-term mma (unchanged from R4)
// ============================================================================
#define ROWB     80
#define ARR_B    (128 * ROWB)
#define STG_B    (4 * ARR_B)
#define SM_BF16  (2 * STG_B)      // 81920

__global__ void __launch_bounds__(256)
pv_kernel(float* __restrict__ outp)
{
    const bf16* Ah = g_Phi + ((size_t)blockIdx.z << 22);
    const bf16* Al = g_Plo + ((size_t)blockIdx.z << 22);
    const bf16* Bh = g_Vthi + ((size_t)blockIdx.z << 21);
    const bf16* Bl = g_Vtlo + ((size_t)blockIdx.z << 21);
    const int lda = 2048, ldb = 2048, K = 2048;

    extern __shared__ char sm[];
    const uint32_t smb = smem_u32(sm);
    const int tid = threadIdx.x, lane = tid & 31, wid = tid >> 5;
    const int wm = wid & 1, wn = wid >> 1;
    const int row0 = blockIdx.y * 128, col0 = blockIdx.x * 128;

    float acc[4][4][4];
    #pragma unroll
    for (int i = 0; i < 4; ++i)
        #pragma unroll
        for (int j = 0; j < 4; ++j)
            #pragma unroll
            for (int k = 0; k < 4; ++k) acc[i][j][k] = 0.f;

    const int lr = tid >> 2;
    const int lk = (tid & 3) * 8;
    const uint32_t soff = lr * ROWB + lk * 2;
    const bf16* pa  = Ah + (size_t)(row0 + lr) * lda + lk;
    const bf16* pal = Al + (size_t)(row0 + lr) * lda + lk;
    const bf16* pb  = Bh + (size_t)(col0 + lr) * ldb + lk;
    const bf16* pbl = Bl + (size_t)(col0 + lr) * ldb + lk;

    auto load_stage = [&](int sbuf, int k0) {
        uint32_t b = smb + sbuf * STG_B + soff;
        cp16(b,                         pa  + k0);
        cp16(b + 64 * ROWB,             pa  + k0 + (size_t)64 * lda);
        cp16(b + ARR_B,                 pal + k0);
        cp16(b + ARR_B + 64 * ROWB,     pal + k0 + (size_t)64 * lda);
        cp16(b + 2 * ARR_B,             pb  + k0);
        cp16(b + 2 * ARR_B + 64 * ROWB, pb  + k0 + (size_t)64 * ldb);
        cp16(b + 3 * ARR_B,             pbl + k0);
        cp16(b + 3 * ARR_B + 64 * ROWB, pbl + k0 + (size_t)64 * ldb);
        CP_COMMIT();
    };

    const int ns = K >> 5;
    load_stage(0, 0);

    const uint32_t a_off = (wm * 64 + (lane & 15)) * ROWB + (lane >> 4) * 16;
    const uint32_t b_off = (wn * 32 + (lane & 7) + ((lane >> 4) << 3)) * ROWB
                         + ((lane >> 3) & 1) * 16;

    for (int s = 0; s < ns; ++s) {
        if (s + 1 < ns) {
            load_stage((s + 1) & 1, (s + 1) * 32);
            asm volatile("cp.async.wait_group 1;" ::: "memory");
        } else {
            asm volatile("cp.async.wait_group 0;" ::: "memory");
        }
        __syncthreads();

        const uint32_t sb = smb + (s & 1) * STG_B;
        #pragma unroll
        for (int ks = 0; ks < 2; ++ks) {
            const uint32_t ab = sb + a_off + ks * 32;
            const uint32_t bb = sb + 2 * ARR_B + b_off + ks * 32;
            uint32_t ah[4][4], al[4][4], bh[2][4], bl[2][4];
            #pragma unroll
            for (int mt = 0; mt < 4; ++mt) {
                ldm4(ah[mt], ab + mt * 16 * ROWB);
                ldm4(al[mt], ab + ARR_B + mt * 16 * ROWB);
            }
            #pragma unroll
            for (int bt = 0; bt < 2; ++bt) {
                ldm4(bh[bt], bb + bt * 16 * ROWB);
                ldm4(bl[bt], bb + ARR_B + bt * 16 * ROWB);
            }
            #pragma unroll
            for (int mt = 0; mt < 4; ++mt)
                #pragma unroll
                for (int nt = 0; nt < 4; ++nt) {
                    const int bt = nt >> 1, h = (nt & 1) * 2;
                    mma_bf16(acc[mt][nt], ah[mt], bh[bt][h], bh[bt][h + 1]);
                    mma_bf16(acc[mt][nt], ah[mt], bl[bt][h], bl[bt][h + 1]);
                    mma_bf16(acc[mt][nt], al[mt], bh[bt][h], bh[bt][h + 1]);
                }
        }
        __syncthreads();
    }

    const int gr0 = row0 + wm * 64 + (lane >> 2);
    const int gc0 = col0 + wn * 32 + (lane & 3) * 2;
    #pragma unroll
    for (int mt = 0; mt < 4; ++mt)
        #pragma unroll
        for (int nt = 0; nt < 4; ++nt) {
            const int gr = gr0 + mt * 16;
            const int gc = gc0 + nt * 8;
            const float* c = acc[mt][nt];
            float* p = outp + ((size_t)blockIdx.z << 21) + (size_t)gr * 1024 + gc;
            *(float2*)p              = make_float2(c[0], c[1]);
            *(float2*)(p + 8 * 1024) = make_float2(c[2], c[3]);
        }
}

// ============================================================================
//                      converts & softmax
// ============================================================================
__global__ void __launch_bounds__(256)
convert_i8_kernel(const float* __restrict__ src, int8_t* __restrict__ d1,
                  int8_t* __restrict__ d2, float S, int n4)
{
    int i = blockIdx.x * blockDim.x + threadIdx.x;
    if (i < n4) {
        float4 v = *(const float4*)(src + i * 4);
        float f[4] = {v.x, v.y, v.z, v.w};
        char h[4], l[4];
        #pragma unroll
        for (int j = 0; j < 4; ++j) {
            int hi, lo;
            quant2(f[j], S, hi, lo);
            h[j] = (char)hi; l[j] = (char)lo;
        }
        *(char4*)(d1 + (size_t)i * 4) = make_char4(h[0], h[1], h[2], h[3]);
        *(char4*)(d2 + (size_t)i * 4) = make_char4(l[0], l[1], l[2], l[3]);
    }
}

__global__ void __launch_bounds__(256)
softmax_kernel()
{
    size_t ro = (size_t)blockIdx.x * 2048;
    const float* p = g_S + ro;
    const int t = threadIdx.x;
    __shared__ float red[8];

    float v[8];
    float m = -1e30f;
    #pragma unroll
    for (int i = 0; i < 8; ++i) {
        v[i] = p[t + i * 256];
        m = fmaxf(m, v[i]);
    }
    #pragma unroll
    for (int o = 16; o; o >>= 1) m = fmaxf(m, __shfl_xor_sync(0xffffffffu, m, o));
    if ((t & 31) == 0) red[t >> 5] = m;
    __syncthreads();
    m = red[0];
    #pragma unroll
    for (int i = 1; i < 8; ++i) m = fmaxf(m, red[i]);
    __syncthreads();

    float s = 0.f;
    #pragma unroll
    for (int i = 0; i < 8; ++i) {
        v[i] = __expf(v[i] - m);
        s += v[i];
    }
    #pragma unroll
    for (int o = 16; o; o >>= 1) s += __shfl_xor_sync(0xffffffffu, s, o);
    if ((t & 31) == 0) red[t >> 5] = s;
    __syncthreads();
    s = red[0];
    #pragma unroll
    for (int i = 1; i < 8; ++i) s += red[i];

    const float inv = 1.0f / s;
    #pragma unroll
    for (int i = 0; i < 8; ++i) {
        float pv = v[i] * inv;
        size_t o = ro + t + i * 256;
        bf16 h = __float2bfloat16(pv);
        g_Phi[o] = h;
        g_Plo[o] = __float2bfloat16(pv - __bfloat162float(h));
    }
}

// ---------------- launch ------------------------------------------------------
extern "C" void kernel_launch(void* const* d_in, const int* in_sizes, int n_in,
                              void* d_out, int out_size)
{
    const float* x  = (const float*)d_in[0];
    const float* Wq = (const float*)d_in[1];
    const float* Wk = (const float*)d_in[2];
    const float* Wv = (const float*)d_in[3];
    float* out = (float*)d_out;

    cudaFuncSetAttribute(qkv_i8_kernel, cudaFuncAttributeMaxDynamicSharedMemorySize, I8_SMEM);
    cudaFuncSetAttribute(qk_i8_kernel,  cudaFuncAttributeMaxDynamicSharedMemorySize, I8_SMEM);
    cudaFuncSetAttribute(pv_kernel,     cudaFuncAttributeMaxDynamicSharedMemorySize, SM_BF16);

    int8_t *x1, *x2, *w1, *w2;
    cudaGetSymbolAddress((void**)&x1, g_x1);
    cudaGetSymbolAddress((void**)&x2, g_x2);
    cudaGetSymbolAddress((void**)&w1, g_W1);
    cudaGetSymbolAddress((void**)&w2, g_W2);

    {
        int n4 = 8192 * 1024 / 4;
        convert_i8_kernel<<<(n4 + 255) / 256, 256>>>(x, x1, x2, S_X, n4);
    }
    {
        int n4 = 1024 * 1024 / 4;
        convert_i8_kernel<<<(n4 + 255) / 256, 256>>>(Wq, w1, w2, S_W, n4);
        convert_i8_kernel<<<(n4 + 255) / 256, 256>>>(Wk, w1 + 1024 * 1024, w2 + 1024 * 1024, S_W, n4);
        convert_i8_kernel<<<(n4 + 255) / 256, 256>>>(Wv, w1 + 2 * 1024 * 1024, w2 + 2 * 1024 * 1024, S_W, n4);
    }

    dim3 g1(16, 64, 3);   // QKV: N=1024/64, M=8192/128
    qkv_i8_kernel<<<g1, 256, I8_SMEM>>>();

    dim3 g2(32, 16, 4);   // QK: N=2048/64, M=2048/128
    qk_i8_kernel<<<g2, 256, I8_SMEM>>>();

    softmax_kernel<<<4 * 2048, 256>>>();

    dim3 g3(8, 16, 4);    // PV: 2048x1024, K=2048
    pv_kernel<<<g3, 256, SM_BF16>>>(out);
}

// round 7
// speedup vs baseline: 3.7995x; 3.7995x over previous
#include <cuda_runtime.h>
#include <cuda_fp16.h>
#include <cstdint>

// ============================================================================
// R7: all GEMMs via fp16 mma.sync m16n8k16 with 2-term split:
//     C = (Ah + Al) * Bh    (A stored as exact fp16 pair, B single fp16)
// Error = one-sided fp16 quantization of B (~1.4e-4 rms/matrix) — calibrated
// by R6 (same structure measured 3.66e-4 total, passed).
// Phases: convert -> QKV -> QK -> softmax -> PV. All NT; V stored transposed.
// mma count = 2/3 of the R4 3-term bf16 scheme -> ~814us GEMM at HMMA ceiling.
// ============================================================================

using fp16 = __half;

// ---------------- scratch ----------------------------------------------------
__device__ __align__(256) fp16 g_xh[8192 * 1024], g_xl[8192 * 1024];
__device__ __align__(256) fp16 g_W[3 * 1024 * 1024];              // single fp16
__device__ __align__(256) fp16 g_Qh[8192 * 1024], g_Ql[8192 * 1024];
__device__ __align__(256) fp16 g_Kh[8192 * 1024];                 // single fp16
__device__ __align__(256) fp16 g_Vt[4 * 1024 * 2048];             // single, transposed
__device__ __align__(256) float g_S[4 * 2048 * 2048];
__device__ __align__(256) fp16 g_Ph[4 * 2048 * 2048], g_Pl[4 * 2048 * 2048];

// ---------------- PTX helpers -------------------------------------------------
__device__ __forceinline__ uint32_t smem_u32(const void* p) {
    uint32_t a;
    asm("{ .reg .u64 t; cvta.to.shared.u64 t, %1; cvt.u32.u64 %0, t; }" : "=r"(a) : "l"(p));
    return a;
}
__device__ __forceinline__ void cp16(uint32_t dst, const void* src) {
    asm volatile("cp.async.cg.shared.global [%0], [%1], 16;" :: "r"(dst), "l"(src));
}
#define CP_COMMIT() asm volatile("cp.async.commit_group;" ::: "memory")

__device__ __forceinline__ void ldm4(uint32_t* r, uint32_t a) {
    asm volatile("ldmatrix.sync.aligned.m8n8.x4.shared.b16 {%0,%1,%2,%3}, [%4];"
                 : "=r"(r[0]), "=r"(r[1]), "=r"(r[2]), "=r"(r[3]) : "r"(a));
}
__device__ __forceinline__ void mma_f16(float* c, const uint32_t* a, uint32_t b0, uint32_t b1) {
    asm volatile(
        "mma.sync.aligned.m16n8k16.row.col.f32.f16.f16.f32 "
        "{%0,%1,%2,%3}, {%4,%5,%6,%7}, {%8,%9}, {%0,%1,%2,%3};"
        : "+f"(c[0]), "+f"(c[1]), "+f"(c[2]), "+f"(c[3])
        : "r"(a[0]), "r"(a[1]), "r"(a[2]), "r"(a[3]), "r"(b0), "r"(b1));
}

__device__ __forceinline__ void pair_store(float v, fp16* hi, fp16* lo, size_t o) {
    fp16 h = __float2half(v);
    hi[o] = h;
    lo[o] = __float2half(v - __half2float(h));
}

// ---------------- SMEM layout -------------------------------------------------
// Per stage: Ah, Al, Bh — each 128 rows x 32 fp16, row stride 40 fp16 (80B):
// conflict-free ldmatrix (r*20 words mod 32 distinct).
#define ROWB     80
#define ARR_B    (128 * ROWB)     // 10240
#define STG_B    (3 * ARR_B)      // 30720
#define SM_TOTAL (2 * STG_B)      // 61440

// ---------------- GEMM body ---------------------------------------------------
// MODE 0: QKV (z: 0->Q fp16 pair, 1->K fp16 single, 2->V fp16 single transposed)
// MODE 1: QK  (z=batch), g_S = acc/32 fp32
// MODE 2: PV  (z=batch), out = acc fp32
template <int MODE>
__device__ __forceinline__ void gemm_body(
    const fp16* __restrict__ Ah, const fp16* __restrict__ Al, int lda,
    const fp16* __restrict__ Bh, int ldb,
    int K, float* __restrict__ outp)
{
    extern __shared__ char sm[];
    const uint32_t smb = smem_u32(sm);
    const int tid = threadIdx.x, lane = tid & 31, wid = tid >> 5;
    const int wm = wid & 1, wn = wid >> 1;          // warp tile: 64x32
    const int row0 = blockIdx.y * 128, col0 = blockIdx.x * 128;

    float acc[4][4][4];
    #pragma unroll
    for (int i = 0; i < 4; ++i)
        #pragma unroll
        for (int j = 0; j < 4; ++j)
            #pragma unroll
            for (int k = 0; k < 4; ++k) acc[i][j][k] = 0.f;

    const int lr = tid >> 2;              // 0..63
    const int lk = (tid & 3) * 8;         // element offset in K
    const uint32_t soff = lr * ROWB + lk * 2;
    const fp16* pa  = Ah + (size_t)(row0 + lr) * lda + lk;
    const fp16* pal = Al + (size_t)(row0 + lr) * lda + lk;
    const fp16* pb  = Bh + (size_t)(col0 + lr) * ldb + lk;

    auto load_stage = [&](int sbuf, int k0) {
        uint32_t b = smb + sbuf * STG_B + soff;
        cp16(b,                         pa  + k0);
        cp16(b + 64 * ROWB,             pa  + k0 + (size_t)64 * lda);
        cp16(b + ARR_B,                 pal + k0);
        cp16(b + ARR_B + 64 * ROWB,     pal + k0 + (size_t)64 * lda);
        cp16(b + 2 * ARR_B,             pb  + k0);
        cp16(b + 2 * ARR_B + 64 * ROWB, pb  + k0 + (size_t)64 * ldb);
        CP_COMMIT();
    };

    const int ns = K >> 5;   // 32 K per stage
    load_stage(0, 0);

    const uint32_t a_off = (wm * 64 + (lane & 15)) * ROWB + (lane >> 4) * 16;
    const uint32_t b_off = (wn * 32 + (lane & 7) + ((lane >> 4) << 3)) * ROWB
                         + ((lane >> 3) & 1) * 16;

    for (int s = 0; s < ns; ++s) {
        if (s + 1 < ns) {
            load_stage((s + 1) & 1, (s + 1) * 32);
            asm volatile("cp.async.wait_group 1;" ::: "memory");
        } else {
            asm volatile("cp.async.wait_group 0;" ::: "memory");
        }
        __syncthreads();

        const uint32_t sb = smb + (s & 1) * STG_B;
        #pragma unroll
        for (int ks = 0; ks < 2; ++ks) {
            const uint32_t ab = sb + a_off + ks * 32;
            const uint32_t bb = sb + 2 * ARR_B + b_off + ks * 32;
            uint32_t ah[4][4], al[4][4], bh[2][4];
            #pragma unroll
            for (int mt = 0; mt < 4; ++mt) {
                ldm4(ah[mt], ab + mt * 16 * ROWB);
                ldm4(al[mt], ab + ARR_B + mt * 16 * ROWB);
            }
            #pragma unroll
            for (int bt = 0; bt < 2; ++bt)
                ldm4(bh[bt], bb + bt * 16 * ROWB);
            #pragma unroll
            for (int mt = 0; mt < 4; ++mt)
                #pragma unroll
                for (int nt = 0; nt < 4; ++nt) {
                    const int bt = nt >> 1, h = (nt & 1) * 2;
                    mma_f16(acc[mt][nt], ah[mt], bh[bt][h], bh[bt][h + 1]);
                    mma_f16(acc[mt][nt], al[mt], bh[bt][h], bh[bt][h + 1]);
                }
        }
        __syncthreads();
    }

    // ---- epilogue ----
    const int z = blockIdx.z;
    const int gr0 = row0 + wm * 64 + (lane >> 2);
    const int gc0 = col0 + wn * 32 + (lane & 3) * 2;

    #pragma unroll
    for (int mt = 0; mt < 4; ++mt)
        #pragma unroll
        for (int nt = 0; nt < 4; ++nt) {
            const int gr = gr0 + mt * 16;
            const int gc = gc0 + nt * 8;
            const float* c = acc[mt][nt];
            if (MODE == 0) {
                if (z == 0) {            // Q: fp16 pair
                    const size_t o = (size_t)gr * 1024 + gc;
                    pair_store(c[0], g_Qh, g_Ql, o);
                    pair_store(c[1], g_Qh, g_Ql, o + 1);
                    pair_store(c[2], g_Qh, g_Ql, o + 8 * 1024);
                    pair_store(c[3], g_Qh, g_Ql, o + 8 * 1024 + 1);
                } else if (z == 1) {     // K: fp16 single
                    const size_t o = (size_t)gr * 1024 + gc;
                    g_Kh[o]            = __float2half(c[0]);
                    g_Kh[o + 1]        = __float2half(c[1]);
                    g_Kh[o + 8 * 1024] = __float2half(c[2]);
                    g_Kh[o + 8 * 1024 + 1] = __float2half(c[3]);
                } else {                 // V: fp16 single, transposed Vt[(b*1024+n)][t]
                    const int b = gr >> 11, t = gr & 2047;
                    const size_t o = ((size_t)(b * 1024 + gc)) * 2048 + t;
                    g_Vt[o]            = __float2half(c[0]);
                    g_Vt[o + 2048]     = __float2half(c[1]);
                    g_Vt[o + 8]        = __float2half(c[2]);
                    g_Vt[o + 2048 + 8] = __float2half(c[3]);
                }
            } else if (MODE == 1) {
                float* p = g_S + ((size_t)z << 22) + (size_t)gr * 2048 + gc;
                *(float2*)p              = make_float2(c[0] * 0.03125f, c[1] * 0.03125f);
                *(float2*)(p + 8 * 2048) = make_float2(c[2] * 0.03125f, c[3] * 0.03125f);
            } else {
                float* p = outp + ((size_t)z << 21) + (size_t)gr * 1024 + gc;
                *(float2*)p              = make_float2(c[0], c[1]);
                *(float2*)(p + 8 * 1024) = make_float2(c[2], c[3]);
            }
        }
}

// ---------------- kernels -----------------------------------------------------
__global__ void __launch_bounds__(256)
qkv_kernel()
{
    const int z = blockIdx.z;
    gemm_body<0>(g_xh, g_xl, 1024,
                 g_W + (size_t)z * 1024 * 1024, 1024,
                 1024, nullptr);
}

__global__ void __launch_bounds__(256)
qk_kernel()
{
    const size_t bo = (size_t)blockIdx.z << 21;   // b*2048*1024
    gemm_body<1>(g_Qh + bo, g_Ql + bo, 1024,
                 g_Kh + bo, 1024,
                 1024, nullptr);
}

__global__ void __launch_bounds__(256)
pv_kernel(float* __restrict__ out)
{
    const size_t ao = (size_t)blockIdx.z << 22;   // b*2048*2048
    const size_t bo = (size_t)blockIdx.z << 21;   // b*1024*2048
    gemm_body<2>(g_Ph + ao, g_Pl + ao, 2048,
                 g_Vt + bo, 2048,
                 2048, out);
}

__global__ void __launch_bounds__(256)
convert_pair_kernel(const float* __restrict__ src, fp16* __restrict__ hi,
                    fp16* __restrict__ lo, int n4)
{
    int i = blockIdx.x * blockDim.x + threadIdx.x;
    if (i < n4) {
        float4 v = *(const float4*)(src + i * 4);
        float f[4] = {v.x, v.y, v.z, v.w};
        #pragma unroll
        for (int j = 0; j < 4; ++j) {
            fp16 h = __float2half(f[j]);
            hi[i * 4 + j] = h;
            lo[i * 4 + j] = __float2half(f[j] - __half2float(h));
        }
    }
}

__global__ void __launch_bounds__(256)
convert_single_kernel(const float* __restrict__ src, fp16* __restrict__ dst, int n4)
{
    int i = blockIdx.x * blockDim.x + threadIdx.x;
    if (i < n4) {
        float4 v = *(const float4*)(src + i * 4);
        __half2* d = (__half2*)(dst + (size_t)i * 4);
        d[0] = __floats2half2_rn(v.x, v.y);
        d[1] = __floats2half2_rn(v.z, v.w);
    }
}

__global__ void __launch_bounds__(256)
softmax_kernel()
{
    size_t ro = (size_t)blockIdx.x * 2048;
    const float* p = g_S + ro;
    const int t = threadIdx.x;
    __shared__ float red[8];

    float v[8];
    float m = -1e30f;
    #pragma unroll
    for (int i = 0; i < 8; ++i) {
        v[i] = p[t + i * 256];
        m = fmaxf(m, v[i]);
    }
    #pragma unroll
    for (int o = 16; o; o >>= 1) m = fmaxf(m, __shfl_xor_sync(0xffffffffu, m, o));
    if ((t & 31) == 0) red[t >> 5] = m;
    __syncthreads();
    m = red[0];
    #pragma unroll
    for (int i = 1; i < 8; ++i) m = fmaxf(m, red[i]);
    __syncthreads();

    float s = 0.f;
    #pragma unroll
    for (int i = 0; i < 8; ++i) {
        v[i] = __expf(v[i] - m);
        s += v[i];
    }
    #pragma unroll
    for (int o = 16; o; o >>= 1) s += __shfl_xor_sync(0xffffffffu, s, o);
    if ((t & 31) == 0) red[t >> 5] = s;
    __syncthreads();
    s = red[0];
    #pragma unroll
    for (int i = 1; i < 8; ++i) s += red[i];

    const float inv = 1.0f / s;
    #pragma unroll
    for (int i = 0; i < 8; ++i) {
        float pv = v[i] * inv;
        size_t o = ro + t + i * 256;
        fp16 h = __float2half(pv);
        g_Ph[o] = h;
        g_Pl[o] = __float2half(pv - __half2float(h));
    }
}

// ---------------- launch ------------------------------------------------------
extern "C" void kernel_launch(void* const* d_in, const int* in_sizes, int n_in,
                              void* d_out, int out_size)
{
    const float* x  = (const float*)d_in[0];
    const float* Wq = (const float*)d_in[1];
    const float* Wk = (const float*)d_in[2];
    const float* Wv = (const float*)d_in[3];
    float* out = (float*)d_out;

    cudaFuncSetAttribute(qkv_kernel, cudaFuncAttributeMaxDynamicSharedMemorySize, SM_TOTAL);
    cudaFuncSetAttribute(qk_kernel,  cudaFuncAttributeMaxDynamicSharedMemorySize, SM_TOTAL);
    cudaFuncSetAttribute(pv_kernel,  cudaFuncAttributeMaxDynamicSharedMemorySize, SM_TOTAL);

    fp16 *xh, *xl, *w;
    cudaGetSymbolAddress((void**)&xh, g_xh);
    cudaGetSymbolAddress((void**)&xl, g_xl);
    cudaGetSymbolAddress((void**)&w,  g_W);

    {
        int n4 = 8192 * 1024 / 4;
        convert_pair_kernel<<<(n4 + 255) / 256, 256>>>(x, xh, xl, n4);
    }
    {
        int n4 = 1024 * 1024 / 4;
        convert_single_kernel<<<(n4 + 255) / 256, 256>>>(Wq, w, n4);
        convert_single_kernel<<<(n4 + 255) / 256, 256>>>(Wk, w + 1024 * 1024, n4);
        convert_single_kernel<<<(n4 + 255) / 256, 256>>>(Wv, w + 2 * 1024 * 1024, n4);
    }

    dim3 g1(8, 64, 3);    // QKV: N=1024/128, M=8192/128
    qkv_kernel<<<g1, 256, SM_TOTAL>>>();

    dim3 g2(16, 16, 4);   // QK: 2048x2048 per batch
    qk_kernel<<<g2, 256, SM_TOTAL>>>();

    softmax_kernel<<<4 * 2048, 256>>>();

    dim3 g3(8, 16, 4);    // PV: 2048x1024, K=2048
    pv_kernel<<<g3, 256, SM_TOTAL>>>(out);
}

// round 8
// speedup vs baseline: 6.6549x; 1.7515x over previous
#include <cuda_runtime.h>
#include <cuda_fp16.h>
#include <cstdint>

// ============================================================================
// R8: all GEMMs pure fp16 mma.sync m16n8k16 (1 term, fp32 accum).
// Error = 6 one-sided fp16 quantizations (x,W,Q,K,P,V) ~2.4e-4 each in
// quadrature -> ~6e-4 predicted (R7 measured 4.25e-4 from 3 sources).
// Phases: convert -> QKV -> QK -> softmax -> PV. All NT; V stored transposed.
// mma count = 1/2 of R7 -> ~355us GEMM at the measured HMMA issue ceiling.
// ============================================================================

using fp16 = __half;

// ---------------- scratch ----------------------------------------------------
__device__ __align__(256) fp16 g_x[8192 * 1024];
__device__ __align__(256) fp16 g_W[3 * 1024 * 1024];
__device__ __align__(256) fp16 g_Q[8192 * 1024];
__device__ __align__(256) fp16 g_K[8192 * 1024];
__device__ __align__(256) fp16 g_Vt[4 * 1024 * 2048];        // transposed
__device__ __align__(256) float g_S[4 * 2048 * 2048];
__device__ __align__(256) fp16 g_P[4 * 2048 * 2048];

// ---------------- PTX helpers -------------------------------------------------
__device__ __forceinline__ uint32_t smem_u32(const void* p) {
    uint32_t a;
    asm("{ .reg .u64 t; cvta.to.shared.u64 t, %1; cvt.u32.u64 %0, t; }" : "=r"(a) : "l"(p));
    return a;
}
__device__ __forceinline__ void cp16(uint32_t dst, const void* src) {
    asm volatile("cp.async.cg.shared.global [%0], [%1], 16;" :: "r"(dst), "l"(src));
}
#define CP_COMMIT() asm volatile("cp.async.commit_group;" ::: "memory")

__device__ __forceinline__ void ldm4(uint32_t* r, uint32_t a) {
    asm volatile("ldmatrix.sync.aligned.m8n8.x4.shared.b16 {%0,%1,%2,%3}, [%4];"
                 : "=r"(r[0]), "=r"(r[1]), "=r"(r[2]), "=r"(r[3]) : "r"(a));
}
__device__ __forceinline__ void mma_f16(float* c, const uint32_t* a, uint32_t b0, uint32_t b1) {
    asm volatile(
        "mma.sync.aligned.m16n8k16.row.col.f32.f16.f16.f32 "
        "{%0,%1,%2,%3}, {%4,%5,%6,%7}, {%8,%9}, {%0,%1,%2,%3};"
        : "+f"(c[0]), "+f"(c[1]), "+f"(c[2]), "+f"(c[3])
        : "r"(a[0]), "r"(a[1]), "r"(a[2]), "r"(a[3]), "r"(b0), "r"(b1));
}

// ---------------- SMEM layout -------------------------------------------------
// Per stage: A, B — each 128 rows x 32 fp16, row stride 40 fp16 (80B):
// conflict-free ldmatrix (r*20 words mod 32 distinct).
#define ROWB     80
#define ARR_B    (128 * ROWB)     // 10240
#define STG_B    (2 * ARR_B)      // 20480
#define SM_TOTAL (2 * STG_B)      // 40960

// ---------------- GEMM body ---------------------------------------------------
// MODE 0: QKV (z: 0->Q, 1->K, 2->V transposed) -> fp16
// MODE 1: QK  (z=batch), g_S = acc/32 fp32
// MODE 2: PV  (z=batch), out = acc fp32
template <int MODE>
__device__ __forceinline__ void gemm_body(
    const fp16* __restrict__ A, int lda,
    const fp16* __restrict__ B, int ldb,
    int K, float* __restrict__ outp)
{
    extern __shared__ char sm[];
    const uint32_t smb = smem_u32(sm);
    const int tid = threadIdx.x, lane = tid & 31, wid = tid >> 5;
    const int wm = wid & 1, wn = wid >> 1;          // warp tile: 64x32
    const int row0 = blockIdx.y * 128, col0 = blockIdx.x * 128;

    float acc[4][4][4];
    #pragma unroll
    for (int i = 0; i < 4; ++i)
        #pragma unroll
        for (int j = 0; j < 4; ++j)
            #pragma unroll
            for (int k = 0; k < 4; ++k) acc[i][j][k] = 0.f;

    const int lr = tid >> 2;              // 0..63
    const int lk = (tid & 3) * 8;         // element offset in K
    const uint32_t soff = lr * ROWB + lk * 2;
    const fp16* pa = A + (size_t)(row0 + lr) * lda + lk;
    const fp16* pb = B + (size_t)(col0 + lr) * ldb + lk;

    auto load_stage = [&](int sbuf, int k0) {
        uint32_t b = smb + sbuf * STG_B + soff;
        cp16(b,                     pa + k0);
        cp16(b + 64 * ROWB,         pa + k0 + (size_t)64 * lda);
        cp16(b + ARR_B,             pb + k0);
        cp16(b + ARR_B + 64 * ROWB, pb + k0 + (size_t)64 * ldb);
        CP_COMMIT();
    };

    const int ns = K >> 5;   // 32 K per stage
    load_stage(0, 0);

    const uint32_t a_off = (wm * 64 + (lane & 15)) * ROWB + (lane >> 4) * 16;
    const uint32_t b_off = (wn * 32 + (lane & 7) + ((lane >> 4) << 3)) * ROWB
                         + ((lane >> 3) & 1) * 16;

    for (int s = 0; s < ns; ++s) {
        if (s + 1 < ns) {
            load_stage((s + 1) & 1, (s + 1) * 32);
            asm volatile("cp.async.wait_group 1;" ::: "memory");
        } else {
            asm volatile("cp.async.wait_group 0;" ::: "memory");
        }
        __syncthreads();

        const uint32_t sb = smb + (s & 1) * STG_B;
        #pragma unroll
        for (int ks = 0; ks < 2; ++ks) {
            const uint32_t ab = sb + a_off + ks * 32;
            const uint32_t bb = sb + ARR_B + b_off + ks * 32;
            uint32_t af[4][4], bf[2][4];
            #pragma unroll
            for (int mt = 0; mt < 4; ++mt)
                ldm4(af[mt], ab + mt * 16 * ROWB);
            #pragma unroll
            for (int bt = 0; bt < 2; ++bt)
                ldm4(bf[bt], bb + bt * 16 * ROWB);
            #pragma unroll
            for (int mt = 0; mt < 4; ++mt)
                #pragma unroll
                for (int nt = 0; nt < 4; ++nt) {
                    const int bt = nt >> 1, h = (nt & 1) * 2;
                    mma_f16(acc[mt][nt], af[mt], bf[bt][h], bf[bt][h + 1]);
                }
        }
        __syncthreads();
    }

    // ---- epilogue ----
    const int z = blockIdx.z;
    const int gr0 = row0 + wm * 64 + (lane >> 2);
    const int gc0 = col0 + wn * 32 + (lane & 3) * 2;

    #pragma unroll
    for (int mt = 0; mt < 4; ++mt)
        #pragma unroll
        for (int nt = 0; nt < 4; ++nt) {
            const int gr = gr0 + mt * 16;
            const int gc = gc0 + nt * 8;
            const float* c = acc[mt][nt];
            if (MODE == 0) {
                if (z == 2) {            // V: fp16, transposed Vt[(b*1024+n)][t]
                    const int b = gr >> 11, t = gr & 2047;
                    const size_t o = ((size_t)(b * 1024 + gc)) * 2048 + t;
                    g_Vt[o]            = __float2half(c[0]);
                    g_Vt[o + 2048]     = __float2half(c[1]);
                    g_Vt[o + 8]        = __float2half(c[2]);
                    g_Vt[o + 2048 + 8] = __float2half(c[3]);
                } else {                 // Q or K: fp16 row-major
                    fp16* d = (z == 0) ? g_Q : g_K;
                    const size_t o = (size_t)gr * 1024 + gc;
                    *(__half2*)(d + o)            = __floats2half2_rn(c[0], c[1]);
                    *(__half2*)(d + o + 8 * 1024) = __floats2half2_rn(c[2], c[3]);
                }
            } else if (MODE == 1) {
                float* p = g_S + ((size_t)z << 22) + (size_t)gr * 2048 + gc;
                *(float2*)p              = make_float2(c[0] * 0.03125f, c[1] * 0.03125f);
                *(float2*)(p + 8 * 2048) = make_float2(c[2] * 0.03125f, c[3] * 0.03125f);
            } else {
                float* p = outp + ((size_t)z << 21) + (size_t)gr * 1024 + gc;
                *(float2*)p              = make_float2(c[0], c[1]);
                *(float2*)(p + 8 * 1024) = make_float2(c[2], c[3]);
            }
        }
}

// ---------------- kernels -----------------------------------------------------
__global__ void __launch_bounds__(256)
qkv_kernel()
{
    const int z = blockIdx.z;
    gemm_body<0>(g_x, 1024, g_W + (size_t)z * 1024 * 1024, 1024, 1024, nullptr);
}

__global__ void __launch_bounds__(256)
qk_kernel()
{
    const size_t bo = (size_t)blockIdx.z << 21;   // b*2048*1024
    gemm_body<1>(g_Q + bo, 1024, g_K + bo, 1024, 1024, nullptr);
}

__global__ void __launch_bounds__(256)
pv_kernel(float* __restrict__ out)
{
    const size_t ao = (size_t)blockIdx.z << 22;   // b*2048*2048
    const size_t bo = (size_t)blockIdx.z << 21;   // b*1024*2048
    gemm_body<2>(g_P + ao, 2048, g_Vt + bo, 2048, 2048, out);
}

__global__ void __launch_bounds__(256)
convert_single_kernel(const float* __restrict__ src, fp16* __restrict__ dst, int n4)
{
    int i = blockIdx.x * blockDim.x + threadIdx.x;
    if (i < n4) {
        float4 v = *(const float4*)(src + i * 4);
        __half2* d = (__half2*)(dst + (size_t)i * 4);
        d[0] = __floats2half2_rn(v.x, v.y);
        d[1] = __floats2half2_rn(v.z, v.w);
    }
}

__global__ void __launch_bounds__(256)
softmax_kernel()
{
    size_t ro = (size_t)blockIdx.x * 2048;
    const float* p = g_S + ro;
    const int t = threadIdx.x;
    __shared__ float red[8];

    float v[8];
    float m = -1e30f;
    #pragma unroll
    for (int i = 0; i < 8; ++i) {
        v[i] = p[t + i * 256];
        m = fmaxf(m, v[i]);
    }
    #pragma unroll
    for (int o = 16; o; o >>= 1) m = fmaxf(m, __shfl_xor_sync(0xffffffffu, m, o));
    if ((t & 31) == 0) red[t >> 5] = m;
    __syncthreads();
    m = red[0];
    #pragma unroll
    for (int i = 1; i < 8; ++i) m = fmaxf(m, red[i]);
    __syncthreads();

    float s = 0.f;
    #pragma unroll
    for (int i = 0; i < 8; ++i) {
        v[i] = __expf(v[i] - m);
        s += v[i];
    }
    #pragma unroll
    for (int o = 16; o; o >>= 1) s += __shfl_xor_sync(0xffffffffu, s, o);
    if ((t & 31) == 0) red[t >> 5] = s;
    __syncthreads();
    s = red[0];
    #pragma unroll
    for (int i = 1; i < 8; ++i) s += red[i];

    const float inv = 1.0f / s;
    #pragma unroll
    for (int i = 0; i < 8; ++i) {
        size_t o = ro + t + i * 256;
        g_P[o] = __float2half(v[i] * inv);
    }
}

// ---------------- launch ------------------------------------------------------
extern "C" void kernel_launch(void* const* d_in, const int* in_sizes, int n_in,
                              void* d_out, int out_size)
{
    const float* x  = (const float*)d_in[0];
    const float* Wq = (const float*)d_in[1];
    const float* Wk = (const float*)d_in[2];
    const float* Wv = (const float*)d_in[3];
    float* out = (float*)d_out;

    cudaFuncSetAttribute(qkv_kernel, cudaFuncAttributeMaxDynamicSharedMemorySize, SM_TOTAL);
    cudaFuncSetAttribute(qk_kernel,  cudaFuncAttributeMaxDynamicSharedMemorySize, SM_TOTAL);
    cudaFuncSetAttribute(pv_kernel,  cudaFuncAttributeMaxDynamicSharedMemorySize, SM_TOTAL);

    fp16 *xp, *w;
    cudaGetSymbolAddress((void**)&xp, g_x);
    cudaGetSymbolAddress((void**)&w,  g_W);

    {
        int n4 = 8192 * 1024 / 4;
        convert_single_kernel<<<(n4 + 255) / 256, 256>>>(x, xp, n4);
    }
    {
        int n4 = 1024 * 1024 / 4;
        convert_single_kernel<<<(n4 + 255) / 256, 256>>>(Wq, w, n4);
        convert_single_kernel<<<(n4 + 255) / 256, 256>>>(Wk, w + 1024 * 1024, n4);
        convert_single_kernel<<<(n4 + 255) / 256, 256>>>(Wv, w + 2 * 1024 * 1024, n4);
    }

    dim3 g1(8, 64, 3);    // QKV: N=1024/128, M=8192/128
    qkv_kernel<<<g1, 256, SM_TOTAL>>>();

    dim3 g2(16, 16, 4);   // QK: 2048x2048 per batch
    qk_kernel<<<g2, 256, SM_TOTAL>>>();

    softmax_kernel<<<4 * 2048, 256>>>();

    dim3 g3(8, 16, 4);    // PV: 2048x1024, K=2048
    pv_kernel<<<g3, 256, SM_TOTAL>>>(out);
}